// round 12
// baseline (speedup 1.0000x reference)
#include <cuda_runtime.h>
#include <cuda_bf16.h>

#define Cc    9
#define OUTc  16
#define NBc   16
#define Vc    20000
#define Bc    2

typedef unsigned long long u64;

__device__ __forceinline__ u64 pk2(float a, float b) {
    u64 r; asm("mov.b64 %0, {%1, %2};" : "=l"(r) : "f"(a), "f"(b)); return r;
}
__device__ __forceinline__ void upk2(u64 v, float& a, float& b) {
    asm("mov.b64 {%0, %1}, %2;" : "=f"(a), "=f"(b) : "l"(v));
}
__device__ __forceinline__ u64 ffma2(u64 a, u64 b, u64 c) {
    u64 d; asm("fma.rn.f32x2 %0, %1, %2, %3;" : "=l"(d) : "l"(a), "l"(b), "l"(c)); return d;
}

// x rows: x0..7 as 2 float4 (32B), x8 separate
__device__ __align__(16) float4 xpad2[Bc * Vc * 2];
__device__ float x8arr[Bc * Vc];

__global__ __launch_bounds__(256)
void pad_kernel(const float* __restrict__ x)
{
    int r = blockIdx.x * blockDim.x + threadIdx.x;
    if (r >= Bc * Vc) return;
    const float* src = x + (size_t)r * Cc;
    xpad2[r * 2 + 0] = make_float4(__ldg(&src[0]), __ldg(&src[1]), __ldg(&src[2]), __ldg(&src[3]));
    xpad2[r * 2 + 1] = make_float4(__ldg(&src[4]), __ldg(&src[5]), __ldg(&src[6]), __ldg(&src[7]));
    x8arr[r] = __ldg(&src[8]);
}

__device__ __forceinline__ void accum_neighbor(
    u64 (&s2)[Cc][4], float (&s8c)[Cc], const float (&xv)[Cc],
    float4 n0, float4 n1, float n8v, int valid)
{
    float nb[Cc] = {n0.x, n0.y, n0.z, n0.w, n1.x, n1.y, n1.z, n1.w, n8v};
    u64 nbp[4] = {pk2(nb[0], nb[1]), pk2(nb[2], nb[3]),
                  pk2(nb[4], nb[5]), pk2(nb[6], nb[7])};
    float e[Cc], sum = 0.0f;
    #pragma unroll
    for (int c = 0; c < Cc; c++) { e[c] = __expf(xv[c] - nb[c]); sum += e[c]; }
    float rr = valid ? __fdividef(1.0f, sum) : 0.0f;
    #pragma unroll
    for (int k = 0; k < Cc; k++) {
        float qk = e[k] * rr;
        u64 qq = pk2(qk, qk);
        s2[k][0] = ffma2(qq, nbp[0], s2[k][0]);
        s2[k][1] = ffma2(qq, nbp[1], s2[k][1]);
        s2[k][2] = ffma2(qq, nbp[2], s2[k][2]);
        s2[k][3] = ffma2(qq, nbp[3], s2[k][3]);
        s8c[k]   = fmaf(qk, nb[8], s8c[k]);
    }
}

__device__ __forceinline__ void finish_and_store(
    u64 (&s2)[Cc][4], float (&s8c)[Cc], int p, float invdeg,
    float* op, const float* Wsh)
{
    // reduce across the lane pair; both lanes get FULL s
    #pragma unroll
    for (int k = 0; k < Cc; k++) {
        #pragma unroll
        for (int j = 0; j < 4; j++) {
            u64 o = __shfl_xor_sync(0xffffffffu, s2[k][j], 1);
            float a0f, a1f, b0f, b1f;
            upk2(s2[k][j], a0f, a1f);
            upk2(o,        b0f, b1f);
            s2[k][j] = pk2(a0f + b0f, a1f + b1f);
        }
        s8c[k] += __shfl_xor_sync(0xffffffffu, s8c[k], 1);
    }

    u64 ac[4] = {0ULL, 0ULL, 0ULL, 0ULL};
    const float* wb = Wsh + 8 * p;
    #pragma unroll
    for (int j = 0; j < 4; j++) {
        #pragma unroll
        for (int k = 0; k < Cc; k++) {
            float sc0, sc1;
            upk2(s2[k][j], sc0, sc1);
            {
                u64 ss = pk2(sc0, sc0);
                const ulonglong2* wr = reinterpret_cast<const ulonglong2*>(
                    wb + ((2 * j) * Cc + k) * OUTc);
                ulonglong2 wA = wr[0], wB = wr[1];
                ac[0] = ffma2(ss, wA.x, ac[0]);
                ac[1] = ffma2(ss, wA.y, ac[1]);
                ac[2] = ffma2(ss, wB.x, ac[2]);
                ac[3] = ffma2(ss, wB.y, ac[3]);
            }
            {
                u64 ss = pk2(sc1, sc1);
                const ulonglong2* wr = reinterpret_cast<const ulonglong2*>(
                    wb + ((2 * j + 1) * Cc + k) * OUTc);
                ulonglong2 wA = wr[0], wB = wr[1];
                ac[0] = ffma2(ss, wA.x, ac[0]);
                ac[1] = ffma2(ss, wA.y, ac[1]);
                ac[2] = ffma2(ss, wB.x, ac[2]);
                ac[3] = ffma2(ss, wB.y, ac[3]);
            }
        }
    }
    #pragma unroll
    for (int k = 0; k < Cc; k++) {       // c = 8
        u64 ss = pk2(s8c[k], s8c[k]);
        const ulonglong2* wr = reinterpret_cast<const ulonglong2*>(
            wb + (8 * Cc + k) * OUTc);
        ulonglong2 wA = wr[0], wB = wr[1];
        ac[0] = ffma2(ss, wA.x, ac[0]);
        ac[1] = ffma2(ss, wA.y, ac[1]);
        ac[2] = ffma2(ss, wB.x, ac[2]);
        ac[3] = ffma2(ss, wB.y, ac[3]);
    }

    float r0f, r1f, r2f, r3f, r4f, r5f, r6f, r7f;
    upk2(ac[0], r0f, r1f);
    upk2(ac[1], r2f, r3f);
    upk2(ac[2], r4f, r5f);
    upk2(ac[3], r6f, r7f);
    float4 o0, o1;
    o0.x = fmaxf(r0f * invdeg, 0.0f);
    o0.y = fmaxf(r1f * invdeg, 0.0f);
    o0.z = fmaxf(r2f * invdeg, 0.0f);
    o0.w = fmaxf(r3f * invdeg, 0.0f);
    o1.x = fmaxf(r4f * invdeg, 0.0f);
    o1.y = fmaxf(r5f * invdeg, 0.0f);
    o1.z = fmaxf(r6f * invdeg, 0.0f);
    o1.w = fmaxf(r7f * invdeg, 0.0f);
    *reinterpret_cast<float4*>(op)     = o0;
    *reinterpret_cast<float4*>(op + 4) = o1;
}

__global__ __launch_bounds__(64, 6)
void nlayer_kernel(const float* __restrict__ W,
                   const int*   __restrict__ adj,
                   float*       __restrict__ out)
{
    __shared__ __align__(16) float Wsh[Cc * Cc * OUTc];
    for (int i = threadIdx.x; i < Cc * Cc * OUTc; i += blockDim.x)
        Wsh[i] = W[i];

    int gid = blockIdx.x * blockDim.x + threadIdx.x;   // 40000 total, exact
    int v   = gid >> 1;            // vertex; this thread handles BOTH batches
    int p   = gid & 1;             // neighbor half AND output half

    const float4* tb0 = xpad2;
    const float*  t80 = x8arr;
    const float4* tb1 = xpad2 + (size_t)Vc * 2;
    const float*  t81 = x8arr + Vc;

    // adjacency once — identical for both batches
    const int4* adj4 = reinterpret_cast<const int4*>(adj + (size_t)v * NBc);
    int4 a0 = __ldg(&adj4[2 * p + 0]);
    int4 a1 = __ldg(&adj4[2 * p + 1]);
    int av[8] = {a0.x, a0.y, a0.z, a0.w, a1.x, a1.y, a1.z, a1.w};
    int ridx[8], deg = 0;
    #pragma unroll
    for (int n = 0; n < 8; n++) {
        int val = (av[n] != 0);
        deg += val;
        ridx[n] = val ? (av[n] - 1) : 0;
    }

    // batch-0 center + all 8 rows in flight
    float4 c0 = __ldg(&tb0[(size_t)v * 2 + 0]);
    float4 c1 = __ldg(&tb0[(size_t)v * 2 + 1]);
    float  cx8 = __ldg(&t80[v]);
    float4 N0[8], N1[8];
    float  N8[8];
    #pragma unroll
    for (int n = 0; n < 8; n++) {
        N0[n] = __ldg(&tb0[(size_t)ridx[n] * 2 + 0]);
        N1[n] = __ldg(&tb0[(size_t)ridx[n] * 2 + 1]);
        N8[n] = __ldg(&t80[ridx[n]]);
    }

    __syncthreads();   // Wsh ready; gather loads above ride over the barrier

    deg += __shfl_xor_sync(0xffffffffu, deg, 1);
    float invdeg = (deg > 0) ? (1.0f / (float)deg) : 0.0f;

    float xv[Cc] = {c0.x, c0.y, c0.z, c0.w, c1.x, c1.y, c1.z, c1.w, cx8};

    u64   s2[Cc][4];
    float s8c[Cc];
    #pragma unroll
    for (int k = 0; k < Cc; k++) {
        s2[k][0] = 0ULL; s2[k][1] = 0ULL; s2[k][2] = 0ULL; s2[k][3] = 0ULL;
        s8c[k] = 0.0f;
    }

    #pragma unroll
    for (int n = 0; n < 8; n++)
        accum_neighbor(s2, s8c, xv, N0[n], N1[n], N8[n], av[n] != 0);

    // ---- prefetch batch-1 center + first 4 rows (covered by A's finish) ----
    c0  = __ldg(&tb1[(size_t)v * 2 + 0]);
    c1  = __ldg(&tb1[(size_t)v * 2 + 1]);
    cx8 = __ldg(&t81[v]);
    #pragma unroll
    for (int n = 0; n < 4; n++) {
        N0[n] = __ldg(&tb1[(size_t)ridx[n] * 2 + 0]);
        N1[n] = __ldg(&tb1[(size_t)ridx[n] * 2 + 1]);
        N8[n] = __ldg(&t81[ridx[n]]);
    }

    // finish batch 0 (~650 cyc of compute hides the prefetch latency)
    finish_and_store(s2, s8c, p, invdeg, out + (size_t)v * OUTc + 8 * p, Wsh);

    // remaining batch-1 rows
    #pragma unroll
    for (int n = 4; n < 8; n++) {
        N0[n] = __ldg(&tb1[(size_t)ridx[n] * 2 + 0]);
        N1[n] = __ldg(&tb1[(size_t)ridx[n] * 2 + 1]);
        N8[n] = __ldg(&t81[ridx[n]]);
    }

    // batch 1
    xv[0] = c0.x; xv[1] = c0.y; xv[2] = c0.z; xv[3] = c0.w;
    xv[4] = c1.x; xv[5] = c1.y; xv[6] = c1.z; xv[7] = c1.w; xv[8] = cx8;

    #pragma unroll
    for (int k = 0; k < Cc; k++) {
        s2[k][0] = 0ULL; s2[k][1] = 0ULL; s2[k][2] = 0ULL; s2[k][3] = 0ULL;
        s8c[k] = 0.0f;
    }

    #pragma unroll
    for (int n = 0; n < 8; n++)
        accum_neighbor(s2, s8c, xv, N0[n], N1[n], N8[n], av[n] != 0);

    finish_and_store(s2, s8c, p, invdeg,
                     out + (size_t)(Vc + v) * OUTc + 8 * p, Wsh);
}

extern "C" void kernel_launch(void* const* d_in, const int* in_sizes, int n_in,
                              void* d_out, int out_size)
{
    const float* x   = (const float*)d_in[0];   // (2, 20000, 9)
    const float* W   = (const float*)d_in[1];   // (9, 9, 16)
    const int*   adj = (const int*)d_in[2];     // (20000, 16)
    float*       out = (float*)d_out;           // (2, 20000, 16)

    {
        const int total   = Bc * Vc;            // 40000
        const int threads = 256;
        pad_kernel<<<(total + threads - 1) / threads, threads>>>(x);
    }
    {
        const int total   = Vc * 2;             // 40000 threads (2 batches each)
        const int threads = 64;
        nlayer_kernel<<<total / threads, threads>>>(W, adj, out);
    }
}

// round 13
// speedup vs baseline: 1.0843x; 1.0843x over previous
#include <cuda_runtime.h>
#include <cuda_bf16.h>

#define Cc    9
#define OUTc  16
#define NBc   16
#define Vc    20000
#define Bc    2

typedef unsigned long long u64;

__device__ __forceinline__ u64 pk2(float a, float b) {
    u64 r; asm("mov.b64 %0, {%1, %2};" : "=l"(r) : "f"(a), "f"(b)); return r;
}
__device__ __forceinline__ void upk2(u64 v, float& a, float& b) {
    asm("mov.b64 {%0, %1}, %2;" : "=f"(a), "=f"(b) : "l"(v));
}
__device__ __forceinline__ u64 ffma2(u64 a, u64 b, u64 c) {
    u64 d; asm("fma.rn.f32x2 %0, %1, %2, %3;" : "=l"(d) : "l"(a), "l"(b), "l"(c)); return d;
}

// padded x: 3 float4 per row (48 B)
__device__ __align__(16) float4 xpad[Bc * Vc * 3];

__global__ __launch_bounds__(256)
void pad_kernel(const float* __restrict__ x)
{
    int r = blockIdx.x * blockDim.x + threadIdx.x;
    if (r >= Bc * Vc) return;
    const float* src = x + (size_t)r * Cc;
    float4* dst = xpad + (size_t)r * 3;
    dst[0] = make_float4(__ldg(&src[0]), __ldg(&src[1]), __ldg(&src[2]), __ldg(&src[3]));
    dst[1] = make_float4(__ldg(&src[4]), __ldg(&src[5]), __ldg(&src[6]), __ldg(&src[7]));
    dst[2] = make_float4(__ldg(&src[8]), 0.0f, 0.0f, 0.0f);
}

__global__ __launch_bounds__(128, 3)
void nlayer_kernel(const float* __restrict__ W,
                   const int*   __restrict__ adj,
                   float*       __restrict__ out)
{
    __shared__ __align__(16) float Wsh[Cc * Cc * OUTc];   // W[c][k][o]
    for (int i = threadIdx.x; i < Cc * Cc * OUTc; i += blockDim.x)
        Wsh[i] = W[i];
    __syncthreads();

    int tid  = blockIdx.x * blockDim.x + threadIdx.x;     // 40064 launched
    bool alive = (tid < Bc * Vc);
    int t    = alive ? tid : 0;
    int b    = (t >= Vc) ? 1 : 0;
    int v    = t - b * Vc;
    const float4* tb = xpad + (size_t)(b * Vc) * 3;

    // center row
    float4 c0 = __ldg(&tb[(size_t)v * 3 + 0]);
    float4 c1 = __ldg(&tb[(size_t)v * 3 + 1]);
    float4 c2 = __ldg(&tb[(size_t)v * 3 + 2]);
    float xv[Cc] = {c0.x, c0.y, c0.z, c0.w, c1.x, c1.y, c1.z, c1.w, c2.x};

    // all 16 neighbor indices
    const int4* adj4 = reinterpret_cast<const int4*>(adj + (size_t)v * NBc);
    int4 a0 = __ldg(&adj4[0]);
    int4 a1 = __ldg(&adj4[1]);
    int4 a2 = __ldg(&adj4[2]);
    int4 a3 = __ldg(&adj4[3]);
    int av[NBc] = {a0.x, a0.y, a0.z, a0.w, a1.x, a1.y, a1.z, a1.w,
                   a2.x, a2.y, a2.z, a2.w, a3.x, a3.y, a3.z, a3.w};

    // s[k][c]: c0..7 packed as 4 f32x2 per k, c=8 scalar
    u64   s2[Cc][4];
    float s8c[Cc];
    #pragma unroll
    for (int k = 0; k < Cc; k++) {
        s2[k][0] = 0ULL; s2[k][1] = 0ULL; s2[k][2] = 0ULL; s2[k][3] = 0ULL;
        s8c[k] = 0.0f;
    }

    int deg = 0;

    // 4 bursts of 4 rows (12 LDG.128 in flight per burst)
    #pragma unroll
    for (int g = 0; g < 4; g++) {
        float4 R0[4], R1[4], R2[4];
        int vld[4];
        #pragma unroll
        for (int n = 0; n < 4; n++) {
            int an = av[g * 4 + n];
            vld[n] = (an != 0);
            deg   += vld[n];
            int ridx = vld[n] ? (an - 1) : 0;
            const float4* nr = tb + (size_t)ridx * 3;
            R0[n] = __ldg(&nr[0]);
            R1[n] = __ldg(&nr[1]);
            R2[n] = __ldg(&nr[2]);
        }

        #pragma unroll
        for (int n = 0; n < 4; n++) {
            float nb[Cc] = {R0[n].x, R0[n].y, R0[n].z, R0[n].w,
                            R1[n].x, R1[n].y, R1[n].z, R1[n].w, R2[n].x};
            u64 nbp[4] = {pk2(nb[0], nb[1]), pk2(nb[2], nb[3]),
                          pk2(nb[4], nb[5]), pk2(nb[6], nb[7])};

            float e[Cc], sum = 0.0f;
            #pragma unroll
            for (int c = 0; c < Cc; c++) {
                e[c] = __expf(xv[c] - nb[c]);
                sum += e[c];
            }
            float rr = vld[n] ? __fdividef(1.0f, sum) : 0.0f;

            #pragma unroll
            for (int k = 0; k < Cc; k++) {
                float qk = e[k] * rr;
                u64 qq = pk2(qk, qk);
                s2[k][0] = ffma2(qq, nbp[0], s2[k][0]);
                s2[k][1] = ffma2(qq, nbp[1], s2[k][1]);
                s2[k][2] = ffma2(qq, nbp[2], s2[k][2]);
                s2[k][3] = ffma2(qq, nbp[3], s2[k][3]);
                s8c[k]   = fmaf(qk, nb[8], s8c[k]);
            }
        }
    }

    float invdeg = (deg > 0) ? (1.0f / (float)deg) : 0.0f;

    // full 16-output contraction, packed accumulators; no reduction needed
    u64 ac[8];
    #pragma unroll
    for (int i = 0; i < 8; i++) ac[i] = 0ULL;

    #pragma unroll
    for (int j = 0; j < 4; j++) {            // c-pairs (2j, 2j+1)
        #pragma unroll
        for (int k = 0; k < Cc; k++) {
            float sc0, sc1;
            upk2(s2[k][j], sc0, sc1);
            {
                u64 ss = pk2(sc0, sc0);
                const ulonglong2* wr = reinterpret_cast<const ulonglong2*>(
                    Wsh + ((2 * j) * Cc + k) * OUTc);
                ulonglong2 wA = wr[0], wB = wr[1];
                ac[0] = ffma2(ss, wA.x, ac[0]);
                ac[1] = ffma2(ss, wA.y, ac[1]);
                ac[2] = ffma2(ss, wB.x, ac[2]);
                ac[3] = ffma2(ss, wB.y, ac[3]);
                ulonglong2 wC = wr[2], wD = wr[3];
                ac[4] = ffma2(ss, wC.x, ac[4]);
                ac[5] = ffma2(ss, wC.y, ac[5]);
                ac[6] = ffma2(ss, wD.x, ac[6]);
                ac[7] = ffma2(ss, wD.y, ac[7]);
            }
            {
                u64 ss = pk2(sc1, sc1);
                const ulonglong2* wr = reinterpret_cast<const ulonglong2*>(
                    Wsh + ((2 * j + 1) * Cc + k) * OUTc);
                ulonglong2 wA = wr[0], wB = wr[1];
                ac[0] = ffma2(ss, wA.x, ac[0]);
                ac[1] = ffma2(ss, wA.y, ac[1]);
                ac[2] = ffma2(ss, wB.x, ac[2]);
                ac[3] = ffma2(ss, wB.y, ac[3]);
                ulonglong2 wC = wr[2], wD = wr[3];
                ac[4] = ffma2(ss, wC.x, ac[4]);
                ac[5] = ffma2(ss, wC.y, ac[5]);
                ac[6] = ffma2(ss, wD.x, ac[6]);
                ac[7] = ffma2(ss, wD.y, ac[7]);
            }
        }
    }
    #pragma unroll
    for (int k = 0; k < Cc; k++) {           // c = 8
        u64 ss = pk2(s8c[k], s8c[k]);
        const ulonglong2* wr = reinterpret_cast<const ulonglong2*>(
            Wsh + (8 * Cc + k) * OUTc);
        ulonglong2 wA = wr[0], wB = wr[1];
        ac[0] = ffma2(ss, wA.x, ac[0]);
        ac[1] = ffma2(ss, wA.y, ac[1]);
        ac[2] = ffma2(ss, wB.x, ac[2]);
        ac[3] = ffma2(ss, wB.y, ac[3]);
        ulonglong2 wC = wr[2], wD = wr[3];
        ac[4] = ffma2(ss, wC.x, ac[4]);
        ac[5] = ffma2(ss, wC.y, ac[5]);
        ac[6] = ffma2(ss, wD.x, ac[6]);
        ac[7] = ffma2(ss, wD.y, ac[7]);
    }

    if (!alive) return;

    // unpack, scale, relu, store 4 coalesced float4 (64B per thread)
    float* op = out + (size_t)t * OUTc;
    #pragma unroll
    for (int i = 0; i < 4; i++) {
        float lo0, hi0, lo1, hi1;
        upk2(ac[2 * i + 0], lo0, hi0);
        upk2(ac[2 * i + 1], lo1, hi1);
        float4 o;
        o.x = fmaxf(lo0 * invdeg, 0.0f);
        o.y = fmaxf(hi0 * invdeg, 0.0f);
        o.z = fmaxf(lo1 * invdeg, 0.0f);
        o.w = fmaxf(hi1 * invdeg, 0.0f);
        *reinterpret_cast<float4*>(op + 4 * i) = o;
    }
}

extern "C" void kernel_launch(void* const* d_in, const int* in_sizes, int n_in,
                              void* d_out, int out_size)
{
    const float* x   = (const float*)d_in[0];   // (2, 20000, 9)
    const float* W   = (const float*)d_in[1];   // (9, 9, 16)
    const int*   adj = (const int*)d_in[2];     // (20000, 16)
    float*       out = (float*)d_out;           // (2, 20000, 16)

    {
        const int total   = Bc * Vc;            // 40000
        const int threads = 256;
        pad_kernel<<<(total + threads - 1) / threads, threads>>>(x);
    }
    {
        const int total   = Bc * Vc;            // 40000 threads
        const int threads = 128;
        nlayer_kernel<<<(total + threads - 1) / threads, threads>>>(W, adj, out);
    }
}

// round 14
// speedup vs baseline: 1.0976x; 1.0122x over previous
#include <cuda_runtime.h>
#include <cuda_bf16.h>

#define Cc    9
#define OUTc  16
#define NBc   16
#define Vc    20000
#define Bc    2

typedef unsigned long long u64;

__device__ __forceinline__ u64 pk2(float a, float b) {
    u64 r; asm("mov.b64 %0, {%1, %2};" : "=l"(r) : "f"(a), "f"(b)); return r;
}
__device__ __forceinline__ void upk2(u64 v, float& a, float& b) {
    asm("mov.b64 {%0, %1}, %2;" : "=f"(a), "=f"(b) : "l"(v));
}
__device__ __forceinline__ u64 ffma2(u64 a, u64 b, u64 c) {
    u64 d; asm("fma.rn.f32x2 %0, %1, %2, %3;" : "=l"(d) : "l"(a), "l"(b), "l"(c)); return d;
}
__device__ __forceinline__ void cpa16(unsigned saddr, const void* gaddr) {
    asm volatile("cp.async.ca.shared.global [%0], [%1], 16;"
                 :: "r"(saddr), "l"(gaddr) : "memory");
}

// x rows: x0..7 as 2 float4 (32B), x8 separate
__device__ __align__(16) float4 xpad2[Bc * Vc * 2];
__device__ float x8arr[Bc * Vc];

__global__ __launch_bounds__(256)
void pad_kernel(const float* __restrict__ x)
{
    int r = blockIdx.x * blockDim.x + threadIdx.x;
    if (r >= Bc * Vc) return;
    const float* src = x + (size_t)r * Cc;
    xpad2[r * 2 + 0] = make_float4(__ldg(&src[0]), __ldg(&src[1]), __ldg(&src[2]), __ldg(&src[3]));
    xpad2[r * 2 + 1] = make_float4(__ldg(&src[4]), __ldg(&src[5]), __ldg(&src[6]), __ldg(&src[7]));
    x8arr[r] = __ldg(&src[8]);
}

#define SLOT 17   // float4 per thread slot (16 data + 1 pad -> conflict-free LDS.128)

__global__ __launch_bounds__(128, 4)
void nlayer_kernel(const float* __restrict__ W,
                   const int*   __restrict__ adj,
                   float*       __restrict__ out)
{
    __shared__ __align__(16) float  Wsh[Cc * Cc * OUTc];   // 5184 B
    __shared__ __align__(16) float4 stage[128 * SLOT];     // 34816 B

    for (int i = threadIdx.x; i < Cc * Cc * OUTc; i += blockDim.x)
        Wsh[i] = W[i];

    int gid   = blockIdx.x * blockDim.x + threadIdx.x;   // 80000 total, exact
    int group = gid >> 1;          // vertex over B*V
    int p     = gid & 1;           // neighbor half AND output half

    int b = (group >= Vc) ? 1 : 0;
    int v = group - b * Vc;
    const float4* tb2 = xpad2 + (size_t)(b * Vc) * 2;
    const float*  tx8 = x8arr + (size_t)(b * Vc);

    // adjacency for this lane's 8 neighbors
    const int4* adj4 = reinterpret_cast<const int4*>(adj + (size_t)v * NBc);
    int4 a0 = __ldg(&adj4[2 * p + 0]);
    int4 a1 = __ldg(&adj4[2 * p + 1]);
    int av[8] = {a0.x, a0.y, a0.z, a0.w, a1.x, a1.y, a1.z, a1.w};

    // center row (merged across the lane pair)
    float4 c0 = __ldg(&tb2[(size_t)v * 2 + 0]);
    float4 c1 = __ldg(&tb2[(size_t)v * 2 + 1]);
    float  cx8 = __ldg(&tx8[v]);

    // stage all 8 neighbor rows via cp.async (zero register cost, MLP 16)
    float4* slot = stage + threadIdx.x * SLOT;
    unsigned sbase = (unsigned)__cvta_generic_to_shared(slot);

    int   deg = 0;
    float N8[8];
    unsigned vmask = 0;
    #pragma unroll
    for (int n = 0; n < 8; n++) {
        int an  = av[n];
        int val = (an != 0);
        deg += val;
        vmask |= (unsigned)val << n;
        int ridx = val ? (an - 1) : 0;
        const float4* g = &tb2[(size_t)ridx * 2];
        cpa16(sbase + (unsigned)(2 * n)     * 16, g);
        cpa16(sbase + (unsigned)(2 * n + 1) * 16, g + 1);
        N8[n] = __ldg(&tx8[ridx]);
    }
    asm volatile("cp.async.commit_group;" ::: "memory");

    __syncthreads();   // Wsh ready (overlaps with in-flight cp.async)

    deg += __shfl_xor_sync(0xffffffffu, deg, 1);
    float invdeg = (deg > 0) ? (1.0f / (float)deg) : 0.0f;

    float xv[Cc] = {c0.x, c0.y, c0.z, c0.w, c1.x, c1.y, c1.z, c1.w, cx8};

    // s[k][c]: c0..7 packed as 4 f32x2 per k, c=8 scalar
    u64   s2[Cc][4];
    float s8c[Cc];
    #pragma unroll
    for (int k = 0; k < Cc; k++) {
        s2[k][0] = 0ULL; s2[k][1] = 0ULL; s2[k][2] = 0ULL; s2[k][3] = 0ULL;
        s8c[k] = 0.0f;
    }

    asm volatile("cp.async.wait_group 0;" ::: "memory");

    #pragma unroll
    for (int n = 0; n < 8; n++) {
        float4 n0 = slot[2 * n + 0];          // conflict-free LDS.128
        float4 n1 = slot[2 * n + 1];
        float nb[Cc] = {n0.x, n0.y, n0.z, n0.w, n1.x, n1.y, n1.z, n1.w, N8[n]};
        u64 nbp[4] = {pk2(nb[0], nb[1]), pk2(nb[2], nb[3]),
                      pk2(nb[4], nb[5]), pk2(nb[6], nb[7])};

        float e[Cc], sum = 0.0f;
        #pragma unroll
        for (int c = 0; c < Cc; c++) {
            e[c] = __expf(xv[c] - nb[c]);
            sum += e[c];
        }
        float rr = (vmask >> n) & 1u ? __fdividef(1.0f, sum) : 0.0f;

        #pragma unroll
        for (int k = 0; k < Cc; k++) {
            float qk = e[k] * rr;
            u64 qq = pk2(qk, qk);
            s2[k][0] = ffma2(qq, nbp[0], s2[k][0]);
            s2[k][1] = ffma2(qq, nbp[1], s2[k][1]);
            s2[k][2] = ffma2(qq, nbp[2], s2[k][2]);
            s2[k][3] = ffma2(qq, nbp[3], s2[k][3]);
            s8c[k]   = fmaf(qk, nb[8], s8c[k]);
        }
    }

    // reduce across the lane pair; both lanes get FULL s
    #pragma unroll
    for (int k = 0; k < Cc; k++) {
        #pragma unroll
        for (int j = 0; j < 4; j++) {
            u64 o = __shfl_xor_sync(0xffffffffu, s2[k][j], 1);
            float x0f, x1f, y0f, y1f;
            upk2(s2[k][j], x0f, x1f);
            upk2(o,        y0f, y1f);
            s2[k][j] = pk2(x0f + y0f, x1f + y1f);
        }
        s8c[k] += __shfl_xor_sync(0xffffffffu, s8c[k], 1);
    }

    // lane p contracts full s into its o-half [8p, 8p+8)
    u64 ac[4] = {0ULL, 0ULL, 0ULL, 0ULL};
    const float* wb = Wsh + 8 * p;
    #pragma unroll
    for (int j = 0; j < 4; j++) {
        #pragma unroll
        for (int k = 0; k < Cc; k++) {
            float sc0, sc1;
            upk2(s2[k][j], sc0, sc1);
            {
                u64 ss = pk2(sc0, sc0);
                const ulonglong2* wr = reinterpret_cast<const ulonglong2*>(
                    wb + ((2 * j) * Cc + k) * OUTc);
                ulonglong2 wA = wr[0], wB = wr[1];
                ac[0] = ffma2(ss, wA.x, ac[0]);
                ac[1] = ffma2(ss, wA.y, ac[1]);
                ac[2] = ffma2(ss, wB.x, ac[2]);
                ac[3] = ffma2(ss, wB.y, ac[3]);
            }
            {
                u64 ss = pk2(sc1, sc1);
                const ulonglong2* wr = reinterpret_cast<const ulonglong2*>(
                    wb + ((2 * j + 1) * Cc + k) * OUTc);
                ulonglong2 wA = wr[0], wB = wr[1];
                ac[0] = ffma2(ss, wA.x, ac[0]);
                ac[1] = ffma2(ss, wA.y, ac[1]);
                ac[2] = ffma2(ss, wB.x, ac[2]);
                ac[3] = ffma2(ss, wB.y, ac[3]);
            }
        }
    }
    #pragma unroll
    for (int k = 0; k < Cc; k++) {          // c = 8
        u64 ss = pk2(s8c[k], s8c[k]);
        const ulonglong2* wr = reinterpret_cast<const ulonglong2*>(
            wb + (8 * Cc + k) * OUTc);
        ulonglong2 wA = wr[0], wB = wr[1];
        ac[0] = ffma2(ss, wA.x, ac[0]);
        ac[1] = ffma2(ss, wA.y, ac[1]);
        ac[2] = ffma2(ss, wB.x, ac[2]);
        ac[3] = ffma2(ss, wB.y, ac[3]);
    }

    // unpack, scale, relu, store two coalesced float4
    float r0f, r1f, r2f, r3f, r4f, r5f, r6f, r7f;
    upk2(ac[0], r0f, r1f);
    upk2(ac[1], r2f, r3f);
    upk2(ac[2], r4f, r5f);
    upk2(ac[3], r6f, r7f);

    float* op = out + (size_t)group * OUTc + 8 * p;
    float4 o0, o1;
    o0.x = fmaxf(r0f * invdeg, 0.0f);
    o0.y = fmaxf(r1f * invdeg, 0.0f);
    o0.z = fmaxf(r2f * invdeg, 0.0f);
    o0.w = fmaxf(r3f * invdeg, 0.0f);
    o1.x = fmaxf(r4f * invdeg, 0.0f);
    o1.y = fmaxf(r5f * invdeg, 0.0f);
    o1.z = fmaxf(r6f * invdeg, 0.0f);
    o1.w = fmaxf(r7f * invdeg, 0.0f);
    *reinterpret_cast<float4*>(op)     = o0;
    *reinterpret_cast<float4*>(op + 4) = o1;
}

extern "C" void kernel_launch(void* const* d_in, const int* in_sizes, int n_in,
                              void* d_out, int out_size)
{
    const float* x   = (const float*)d_in[0];   // (2, 20000, 9)
    const float* W   = (const float*)d_in[1];   // (9, 9, 16)
    const int*   adj = (const int*)d_in[2];     // (20000, 16)
    float*       out = (float*)d_out;           // (2, 20000, 16)

    {
        const int total   = Bc * Vc;            // 40000
        const int threads = 256;
        pad_kernel<<<(total + threads - 1) / threads, threads>>>(x);
    }
    {
        const int total   = Bc * Vc * 2;        // 80000 threads
        const int threads = 128;
        nlayer_kernel<<<total / threads, threads>>>(W, adj, out);
    }
}